// round 16
// baseline (speedup 1.0000x reference)
#include <cuda_runtime.h>
#include <cuda_bf16.h>
#include <math.h>

#define N_NODES 50000
#define N_EDGES 800000
#define DD      128
#define EPSBN   1e-5f

#define TM 64                     // rows per GEMM tile
#define AST 136                   // A-tile row stride in bf16 units (conflict-free)

// dynamic smem layout (float units)
#define OFF_WP    0               // uint4[4096] = 64KB = 16384 floats
#define OFF_AHI   16384           // 64*136 ushort = 4352 floats
#define OFF_ALO   (OFF_AHI + 4352)
#define OFF_BS    (OFF_ALO + 4352)
#define SM_FLOATS (OFF_BS + 128 + 16)
#define SM_BYTES  (SM_FLOATS * 4)   // ~100.9 KB -> 2 blocks/SM

// GEMM-all grid split
#define EDGE_BLKS 1184
#define NODE_BLKS_PER 74          // per weight matrix (4 matrices)
#define ALL_BLKS (EDGE_BLKS + 4 * NODE_BLKS_PER)   // 1480

// ---------------- scratch (static device allocations) ----------------
__device__ float g_Ah[N_NODES * DD];
__device__ float g_Bh[N_NODES * DD];
__device__ float g_Dh[N_NODES * DD];
__device__ float g_Eh[N_NODES * DD];
__device__ float g_hpre[N_NODES * DD];
__device__ float g_enew[(size_t)N_EDGES * DD];
__device__ float g_stats[512];
__device__ float g_bn[512];
__device__ int   g_deg[N_NODES];
__device__ int   g_start[N_NODES + 1];
__device__ int   g_cursor[N_NODES];
__device__ int   g_perm[N_EDGES];

// ---------------- bf16 helpers ----------------
static __device__ __forceinline__ unsigned pack_bf2(float x, float y)
{
    __nv_bfloat162 t = __floats2bfloat162_rn(x, y);
    return *(unsigned*)&t;
}
static __device__ __forceinline__ float ubf_lo(unsigned u) { return __uint_as_float(u << 16); }
static __device__ __forceinline__ float ubf_hi(unsigned u) { return __uint_as_float(u & 0xffff0000u); }

static __device__ __forceinline__ void mma_bf16(float c[4],
    unsigned a0, unsigned a1, unsigned a2, unsigned a3,
    unsigned b0, unsigned b1)
{
    asm("mma.sync.aligned.m16n8k16.row.col.f32.bf16.bf16.f32 "
        "{%0,%1,%2,%3}, {%4,%5,%6,%7}, {%8,%9}, {%0,%1,%2,%3};"
        : "+f"(c[0]), "+f"(c[1]), "+f"(c[2]), "+f"(c[3])
        : "r"(a0), "r"(a1), "r"(a2), "r"(a3), "r"(b0), "r"(b1));
}

// Pack W (row-major [j][k], 128x128) into frag-ready bf16 hi/lo uint4.
static __device__ void build_wp_bf(const float* __restrict__ W, uint4* __restrict__ Wp, int tid)
{
    for (int idx = tid; idx < 4096; idx += 256) {
        int lane = idx & 31, ks = (idx >> 5) & 7, t = idx >> 8;
        int g = lane >> 2, tig = lane & 3;
        int j = t * 8 + g;
        int k0 = ks * 16 + 2 * tig;
        float w00 = W[j * 128 + k0],     w01 = W[j * 128 + k0 + 1];
        float w10 = W[j * 128 + k0 + 8], w11 = W[j * 128 + k0 + 9];
        unsigned b0h = pack_bf2(w00, w01);
        unsigned b1h = pack_bf2(w10, w11);
        unsigned b0l = pack_bf2(w00 - ubf_lo(b0h), w01 - ubf_hi(b0h));
        unsigned b1l = pack_bf2(w10 - ubf_lo(b1h), w11 - ubf_hi(b1h));
        Wp[idx] = make_uint4(b0h, b1h, b0l, b1l);
    }
}

// LDG one 64-row tile slice into registers (8 float4 per thread)
static __device__ __forceinline__ void ldg_tile(const float* __restrict__ A, int base, int M,
                                                int tid, float4 v[8])
{
    #pragma unroll
    for (int i = 0; i < 8; i++) {
        int f4 = tid + i * 256;            // 0..2047
        int row = f4 >> 5, c4 = (f4 & 31) * 4;
        v[i] = make_float4(0.f, 0.f, 0.f, 0.f);
        if (base + row < M) v[i] = *(const float4*)&A[(size_t)(base + row) * 128 + c4];
    }
}

// split registers into bf16 hi/lo smem tiles
static __device__ __forceinline__ void store_split(const float4 v[8],
                                                   unsigned short* __restrict__ Ahi,
                                                   unsigned short* __restrict__ Alo, int tid)
{
    #pragma unroll
    for (int i = 0; i < 8; i++) {
        int f4 = tid + i * 256;
        int row = f4 >> 5, c4 = (f4 & 31) * 4;
        unsigned h01 = pack_bf2(v[i].x, v[i].y);
        unsigned h23 = pack_bf2(v[i].z, v[i].w);
        unsigned l01 = pack_bf2(v[i].x - ubf_lo(h01), v[i].y - ubf_hi(h01));
        unsigned l23 = pack_bf2(v[i].z - ubf_lo(h23), v[i].w - ubf_hi(h23));
        *(uint2*)&Ahi[row * AST + c4] = make_uint2(h01, h23);
        *(uint2*)&Alo[row * AST + c4] = make_uint2(l01, l23);
    }
}

// bf16 3-term split mainloop. Warp tile m32 x n32 (2 mtiles x 4 ntiles), k16 steps.
static __device__ __forceinline__ void mma_mainloop_bf(
    const unsigned short* __restrict__ Ahi, const unsigned short* __restrict__ Alo,
    const uint4* __restrict__ Wp,
    int mwarp, int nwarp, int lane, float acc[2][4][4])
{
    int g = lane >> 2, tig = lane & 3;
    #pragma unroll
    for (int mt = 0; mt < 2; mt++)
        #pragma unroll
        for (int nt = 0; nt < 4; nt++)
            #pragma unroll
            for (int q = 0; q < 4; q++) acc[mt][nt][q] = 0.f;

    #pragma unroll
    for (int ks = 0; ks < 8; ks++) {
        int k0 = ks * 16;
        unsigned ah[2][4], al[2][4];
        #pragma unroll
        for (int mt = 0; mt < 2; mt++) {
            int r0 = mwarp * 32 + mt * 16 + g;
            const unsigned short* ph = Ahi + r0 * AST + k0;
            const unsigned short* pl = Alo + r0 * AST + k0;
            ah[mt][0] = *(const unsigned*)&ph[2 * tig];
            ah[mt][1] = *(const unsigned*)&ph[8 * AST + 2 * tig];
            ah[mt][2] = *(const unsigned*)&ph[2 * tig + 8];
            ah[mt][3] = *(const unsigned*)&ph[8 * AST + 2 * tig + 8];
            al[mt][0] = *(const unsigned*)&pl[2 * tig];
            al[mt][1] = *(const unsigned*)&pl[8 * AST + 2 * tig];
            al[mt][2] = *(const unsigned*)&pl[2 * tig + 8];
            al[mt][3] = *(const unsigned*)&pl[8 * AST + 2 * tig + 8];
        }
        #pragma unroll
        for (int nt = 0; nt < 4; nt++) {
            int t = nwarp * 4 + nt;
            uint4 w = Wp[(t * 8 + ks) * 32 + lane];
            #pragma unroll
            for (int mt = 0; mt < 2; mt++) {
                mma_bf16(acc[mt][nt], ah[mt][0], ah[mt][1], ah[mt][2], ah[mt][3], w.x, w.y);
                mma_bf16(acc[mt][nt], ah[mt][0], ah[mt][1], ah[mt][2], ah[mt][3], w.z, w.w);
                mma_bf16(acc[mt][nt], al[mt][0], al[mt][1], al[mt][2], al[mt][3], w.x, w.y);
            }
        }
    }
}

// ---------------------------------------------------------------------
// All-GEMM kernel: edge GEMM (blocks [0,1184)) + 4 node GEMMs (74 each).
// out = A @ W^T + b, persistent strided tiles, register-prefetch pipeline.
// ---------------------------------------------------------------------
__global__ __launch_bounds__(256, 2) void gemm_all_kernel(
    const float* __restrict__ h, const float* __restrict__ e,
    const float* __restrict__ WA, const float* __restrict__ bA, float* __restrict__ oA,
    const float* __restrict__ WB, const float* __restrict__ bB, float* __restrict__ oB,
    const float* __restrict__ WD, const float* __restrict__ bD, float* __restrict__ oD,
    const float* __restrict__ WE, const float* __restrict__ bE, float* __restrict__ oE,
    const float* __restrict__ WC, const float* __restrict__ bC, float* __restrict__ oC)
{
    extern __shared__ float s[];
    uint4* Wp = (uint4*)(s + OFF_WP);
    unsigned short* Ahi = (unsigned short*)(s + OFF_AHI);
    unsigned short* Alo = (unsigned short*)(s + OFF_ALO);
    float* bs = s + OFF_BS;

    int tid = threadIdx.x, lane = tid & 31, warp = tid >> 5;
    int mwarp = warp >> 2, nwarp = warp & 3;
    int g = lane >> 2, tig = lane & 3;

    const float* A; const float* W; const float* bias; float* out;
    int M, tiles, tstart, tstride;
    if (blockIdx.x < EDGE_BLKS) {
        A = e; W = WC; bias = bC; out = oC;
        M = N_EDGES; tiles = N_EDGES / TM;           // 12500
        tstart = blockIdx.x; tstride = EDGE_BLKS;
    } else {
        int b = blockIdx.x - EDGE_BLKS;
        int which = b / NODE_BLKS_PER;
        A = h; M = N_NODES; tiles = (N_NODES + TM - 1) / TM;   // 782
        tstart = b % NODE_BLKS_PER; tstride = NODE_BLKS_PER;
        if      (which == 0) { W = WA; bias = bA; out = oA; }
        else if (which == 1) { W = WB; bias = bB; out = oB; }
        else if (which == 2) { W = WD; bias = bD; out = oD; }
        else                 { W = WE; bias = bE; out = oE; }
    }

    build_wp_bf(W, Wp, tid);
    if (tid < 128) bs[tid] = bias[tid];

    float4 v[8];
    if (tstart < tiles) ldg_tile(A, tstart * TM, M, tid, v);   // prefetch first tile

    for (int tile = tstart; tile < tiles; tile += tstride) {
        int base = tile * TM;
        __syncthreads();                   // prev MMA done reading smem
        store_split(v, Ahi, Alo, tid);
        __syncthreads();

        int next = tile + tstride;
        if (next < tiles) ldg_tile(A, next * TM, M, tid, v);   // hide under MMA

        float acc[2][4][4];
        mma_mainloop_bf(Ahi, Alo, Wp, mwarp, nwarp, lane, acc);

        #pragma unroll
        for (int mt = 0; mt < 2; mt++) {
            int r0 = base + mwarp * 32 + mt * 16 + g;
            #pragma unroll
            for (int nt = 0; nt < 4; nt++) {
                int col = nwarp * 32 + nt * 8 + 2 * tig;
                float bx = bs[col], by = bs[col + 1];
                if (r0 < M)
                    *(float2*)&out[(size_t)r0 * 128 + col] =
                        make_float2(acc[mt][nt][0] + bx, acc[mt][nt][1] + by);
                if (r0 + 8 < M)
                    *(float2*)&out[(size_t)(r0 + 8) * 128 + col] =
                        make_float2(acc[mt][nt][2] + bx, acc[mt][nt][3] + by);
            }
        }
    }
}

// ---------------------------------------------------------------------
// dst-sort: histogram -> scan -> scatter
// ---------------------------------------------------------------------
__global__ void hist_kernel(const int* __restrict__ dst)
{
    int i = blockIdx.x * blockDim.x + threadIdx.x;
    int stride = gridDim.x * blockDim.x;
    for (; i < N_EDGES; i += stride) atomicAdd(&g_deg[dst[i]], 1);
}

__global__ __launch_bounds__(1024) void scan_kernel()
{
    __shared__ int ssum[1024];
    int t = threadIdx.x;
    const int C = (N_NODES + 1023) / 1024;    // 49
    int lo = t * C, hi = min(lo + C, N_NODES);
    int sum = 0;
    for (int i = lo; i < hi; i++) sum += g_deg[i];
    ssum[t] = sum;
    __syncthreads();
    for (int off = 1; off < 1024; off <<= 1) {
        int v = (t >= off) ? ssum[t - off] : 0;
        __syncthreads();
        ssum[t] += v;
        __syncthreads();
    }
    int run = ssum[t] - sum;    // exclusive prefix of this chunk
    for (int i = lo; i < hi; i++) {
        g_start[i] = run;
        g_cursor[i] = run;
        run += g_deg[i];
    }
    if (t == 1023) g_start[N_NODES] = run;
}

__global__ void scatter_kernel(const int* __restrict__ dst)
{
    int i = blockIdx.x * blockDim.x + threadIdx.x;
    int stride = gridDim.x * blockDim.x;
    for (; i < N_EDGES; i += stride) {
        int p = atomicAdd(&g_cursor[dst[i]], 1);
        g_perm[p] = i;
    }
}

// ---------------------------------------------------------------------
// Edge epilogue v2: one warp per dst node. No atomics for hsum.
// enew holds Ce+bC on entry; rewritten with final e_new.
// Also writes hpre = Ah + sum and accumulates BOTH e- and h-stats.
// ---------------------------------------------------------------------
__global__ __launch_bounds__(256) void edge_epilogue2_kernel(
    float* __restrict__ enew, const float* __restrict__ Ah,
    const float* __restrict__ Bh, const float* __restrict__ Dh, const float* __restrict__ Eh,
    const int* __restrict__ src, const int* __restrict__ mask,
    const float* __restrict__ diff, const float* __restrict__ dist, const float* __restrict__ dirn,
    float* __restrict__ hpre, float* __restrict__ stats)
{
    __shared__ float rs[1024], rq[1024], rsh[1024], rqh[1024];
    int tid = threadIdx.x, lane = tid & 31, warp = tid >> 5;
    int c0 = lane * 4;
    int d = blockIdx.x * 8 + warp;

    float4 csum = make_float4(0.f, 0.f, 0.f, 0.f);
    float4 csq  = make_float4(0.f, 0.f, 0.f, 0.f);
    float4 hsm  = make_float4(0.f, 0.f, 0.f, 0.f);
    float4 hsq  = make_float4(0.f, 0.f, 0.f, 0.f);

    if (d < N_NODES) {
        int s0 = __ldg(&g_start[d]), s1 = __ldg(&g_start[d + 1]);
        float4 dh = *(const float4*)&Dh[(size_t)d * 128 + c0];
        float vd0 = __ldg(&dirn[2 * d]), vd1 = __ldg(&dirn[2 * d + 1]);
        float4 acc = make_float4(0.f, 0.f, 0.f, 0.f);

        for (int j = s0; j < s1; j++) {
            int i = __ldg(&g_perm[j]);
            int si = __ldg(&src[i]);
            float4 ce  = *(const float4*)&enew[(size_t)i * 128 + c0];
            float4 ehv = *(const float4*)&Eh[(size_t)si * 128 + c0];
            float4 de = make_float4(dh.x - ehv.x, dh.y - ehv.y, dh.z - ehv.z, dh.w - ehv.w);
            float4 en = make_float4(de.x + ce.x, de.y + ce.y, de.z + ce.z, de.w + ce.w);

            float ss = en.x * en.x + en.y * en.y + en.z * en.z + en.w * en.w;
            #pragma unroll
            for (int o = 16; o > 0; o >>= 1) ss += __shfl_xor_sync(0xffffffffu, ss, o);
            float sigma = expf(-0.5f * sqrtf(ss));

            float ddv = __ldg(&dist[i]);
            float df0 = __ldg(&diff[2 * i]), df1 = __ldg(&diff[2 * i + 1]);
            float ed0, ed1;
            if (ddv > 0.f) { ed0 = df0 / ddv; ed1 = df1 / ddv; } else { ed0 = df0; ed1 = df1; }
            float vs0 = __ldg(&dirn[2 * si]), vs1 = __ldg(&dirn[2 * si + 1]);
            float uv  = vs0 * vd0 + vs1 * vd1;
            float ehd = ed0 * vd0 + ed1 * vd1;
            float fgate = 0.5f * (1.f - ehd) * uv * sigma;
            float gate = (__ldg(&mask[i]) == 1) ? fgate : sigma;

            float4 bh = *(const float4*)&Bh[(size_t)si * 128 + c0];
            acc.x += (bh.x + de.x) * gate;
            acc.y += (bh.y + de.y) * gate;
            acc.z += (bh.z + de.z) * gate;
            acc.w += (bh.w + de.w) * gate;

            *(float4*)&enew[(size_t)i * 128 + c0] = en;

            csum.x += en.x; csum.y += en.y; csum.z += en.z; csum.w += en.w;
            csq.x += en.x * en.x; csq.y += en.y * en.y;
            csq.z += en.z * en.z; csq.w += en.w * en.w;
        }

        float4 a = *(const float4*)&Ah[(size_t)d * 128 + c0];
        float4 p = make_float4(a.x + acc.x, a.y + acc.y, a.z + acc.z, a.w + acc.w);
        *(float4*)&hpre[(size_t)d * 128 + c0] = p;
        hsm = p;
        hsq = make_float4(p.x * p.x, p.y * p.y, p.z * p.z, p.w * p.w);
    }

    *(float4*)&rs[warp * 128 + c0]  = csum;
    *(float4*)&rq[warp * 128 + c0]  = csq;
    *(float4*)&rsh[warp * 128 + c0] = hsm;
    *(float4*)&rqh[warp * 128 + c0] = hsq;
    __syncthreads();
    if (tid < 128) {
        float s1 = 0.f, q1 = 0.f, s2 = 0.f, q2 = 0.f;
        #pragma unroll
        for (int w = 0; w < 8; w++) {
            s1 += rs[w * 128 + tid];  q1 += rq[w * 128 + tid];
            s2 += rsh[w * 128 + tid]; q2 += rqh[w * 128 + tid];
        }
        atomicAdd(&stats[tid], s1);
        atomicAdd(&stats[128 + tid], q1);
        atomicAdd(&stats[256 + tid], s2);
        atomicAdd(&stats[384 + tid], q2);
    }
}

// ---------------------------------------------------------------------
__global__ void finalize_kernel(const float* __restrict__ st, float* __restrict__ bnout, float invcount)
{
    int t = threadIdx.x;
    if (t < 128) {
        float mean = st[t] * invcount;
        float var  = st[128 + t] * invcount - mean * mean;
        bnout[t] = mean;
        bnout[128 + t] = rsqrtf(var + EPSBN);
    }
}

// out = resid + relu(gamma*(pre-mean)*invstd + beta), elementwise, float4
__global__ void apply_kernel(const float* __restrict__ pre, const float* __restrict__ resid,
                             const float* __restrict__ gamma, const float* __restrict__ beta,
                             const float* __restrict__ bn, float* __restrict__ out, int total4)
{
    int idx = blockIdx.x * blockDim.x + threadIdx.x;
    int stride = gridDim.x * blockDim.x;
    for (; idx < total4; idx += stride) {
        int c0 = (idx & 31) * 4;
        float4 m  = *(const float4*)&bn[c0];
        float4 iv = *(const float4*)&bn[128 + c0];
        float4 g  = *(const float4*)&gamma[c0];
        float4 b  = *(const float4*)&beta[c0];
        float4 p  = ((const float4*)pre)[idx];
        float4 rr = ((const float4*)resid)[idx];
        float4 o;
        o.x = fmaxf((p.x - m.x) * iv.x * g.x + b.x, 0.f) + rr.x;
        o.y = fmaxf((p.y - m.y) * iv.y * g.y + b.y, 0.f) + rr.y;
        o.z = fmaxf((p.z - m.z) * iv.z * g.z + b.z, 0.f) + rr.z;
        o.w = fmaxf((p.w - m.w) * iv.w * g.w + b.w, 0.f) + rr.w;
        ((float4*)out)[idx] = o;
    }
}

// ---------------------------------------------------------------------
extern "C" void kernel_launch(void* const* d_in, const int* in_sizes, int n_in,
                              void* d_out, int out_size)
{
    const float* h    = (const float*)d_in[0];
    const float* e    = (const float*)d_in[1];
    const int*   src  = (const int*)d_in[2];
    const int*   dst  = (const int*)d_in[3];
    const int*   mask = (const int*)d_in[4];
    const float* diff = (const float*)d_in[5];
    const float* dist = (const float*)d_in[6];
    const float* dirn = (const float*)d_in[7];
    const float* WA = (const float*)d_in[8];   const float* bA = (const float*)d_in[9];
    const float* WB = (const float*)d_in[10];  const float* bB = (const float*)d_in[11];
    const float* WC = (const float*)d_in[12];  const float* bC = (const float*)d_in[13];
    const float* WD = (const float*)d_in[14];  const float* bD = (const float*)d_in[15];
    const float* WE = (const float*)d_in[16];  const float* bE = (const float*)d_in[17];
    const float* gh = (const float*)d_in[18];  const float* betah = (const float*)d_in[19];
    const float* ge = (const float*)d_in[20];  const float* betae = (const float*)d_in[21];
    float* out = (float*)d_out;

    float *Ah, *Bh, *Dh, *Eh, *hpre, *enew, *stats, *bn;
    int *deg;
    cudaGetSymbolAddress((void**)&Ah,   g_Ah);
    cudaGetSymbolAddress((void**)&Bh,   g_Bh);
    cudaGetSymbolAddress((void**)&Dh,   g_Dh);
    cudaGetSymbolAddress((void**)&Eh,   g_Eh);
    cudaGetSymbolAddress((void**)&hpre, g_hpre);
    cudaGetSymbolAddress((void**)&enew, g_enew);
    cudaGetSymbolAddress((void**)&stats, g_stats);
    cudaGetSymbolAddress((void**)&bn,   g_bn);
    cudaGetSymbolAddress((void**)&deg,  g_deg);

    cudaFuncSetAttribute(gemm_all_kernel, cudaFuncAttributeMaxDynamicSharedMemorySize, SM_BYTES);

    cudaMemsetAsync(stats, 0, 512 * sizeof(float));                   // launch 1
    cudaMemsetAsync(deg, 0, N_NODES * sizeof(int));                   // launch 2

    hist_kernel<<<800, 256>>>(dst);                                   // launch 3
    scan_kernel<<<1, 1024>>>();                                       // launch 4
    scatter_kernel<<<800, 256>>>(dst);                                // launch 5

    gemm_all_kernel<<<ALL_BLKS, 256, SM_BYTES>>>(                     // launch 6 (ncu captures)
        h, e,
        WA, bA, Ah,
        WB, bB, Bh,
        WD, bD, Dh,
        WE, bE, Eh,
        WC, bC, enew);

    edge_epilogue2_kernel<<<(N_NODES + 7) / 8, 256>>>(                // launch 7
        enew, Ah, Bh, Dh, Eh, src, mask, diff, dist, dirn, hpre, stats);

    finalize_kernel<<<1, 128>>>(stats, bn, 1.0f / (float)N_EDGES);            // e BN
    finalize_kernel<<<1, 128>>>(stats + 256, bn + 256, 1.0f / (float)N_NODES); // h BN

    apply_kernel<<<1024, 256>>>(hpre, h, gh, betah, bn + 256, out, N_NODES * 32);
    apply_kernel<<<4096, 256>>>(enew, e, ge, betae, bn, out + (size_t)N_NODES * DD, N_EDGES * 32);
}

// round 17
// speedup vs baseline: 1.2210x; 1.2210x over previous
#include <cuda_runtime.h>
#include <cuda_bf16.h>
#include <math.h>

#define N_NODES 50000
#define N_EDGES 800000
#define DD      128
#define EPSBN   1e-5f

#define TM 64                     // rows per GEMM tile
#define AST 136                   // A-tile row stride in bf16 units (conflict-free)

// dynamic smem layout (float units)
#define OFF_WP    0               // uint4[4096] = 64KB = 16384 floats
#define OFF_AHI   16384           // 64*136 ushort = 4352 floats
#define OFF_ALO   (OFF_AHI + 4352)
#define OFF_BS    (OFF_ALO + 4352)
#define SM_FLOATS (OFF_BS + 128 + 16)
#define SM_BYTES  (SM_FLOATS * 4)   // ~100.9 KB -> 2 blocks/SM

// GEMM-all grid split
#define EDGE_BLKS 1184
#define NODE_BLKS_PER 74          // per weight matrix (4 matrices)
#define ALL_BLKS (EDGE_BLKS + 4 * NODE_BLKS_PER)   // 1480

// ---------------- scratch (static device allocations) ----------------
__device__ float g_Ah[N_NODES * DD];
__device__ float g_Bh[N_NODES * DD];
__device__ float g_Dh[N_NODES * DD];
__device__ float g_Eh[N_NODES * DD];
__device__ float g_hsum[N_NODES * DD];
__device__ float g_hpre[N_NODES * DD];
__device__ float g_enew[(size_t)N_EDGES * DD];
__device__ float g_stats[512];
__device__ float g_bn[512];

// ---------------- bf16 helpers ----------------
static __device__ __forceinline__ unsigned pack_bf2(float x, float y)
{
    __nv_bfloat162 t = __floats2bfloat162_rn(x, y);
    return *(unsigned*)&t;
}
static __device__ __forceinline__ float ubf_lo(unsigned u) { return __uint_as_float(u << 16); }
static __device__ __forceinline__ float ubf_hi(unsigned u) { return __uint_as_float(u & 0xffff0000u); }

static __device__ __forceinline__ void mma_bf16(float c[4],
    unsigned a0, unsigned a1, unsigned a2, unsigned a3,
    unsigned b0, unsigned b1)
{
    asm("mma.sync.aligned.m16n8k16.row.col.f32.bf16.bf16.f32 "
        "{%0,%1,%2,%3}, {%4,%5,%6,%7}, {%8,%9}, {%0,%1,%2,%3};"
        : "+f"(c[0]), "+f"(c[1]), "+f"(c[2]), "+f"(c[3])
        : "r"(a0), "r"(a1), "r"(a2), "r"(a3), "r"(b0), "r"(b1));
}

// ldmatrix x4: loads 4 8x8 b16 tiles; tile order matches m16n8k16 A-frag regs
static __device__ __forceinline__ void ldsm_x4(unsigned r[4], const void* p)
{
    unsigned addr = (unsigned)__cvta_generic_to_shared(p);
    asm volatile("ldmatrix.sync.aligned.m8n8.x4.shared.b16 {%0,%1,%2,%3}, [%4];"
        : "=r"(r[0]), "=r"(r[1]), "=r"(r[2]), "=r"(r[3]) : "r"(addr));
}

// Pack W (row-major [j][k], 128x128) into frag-ready bf16 hi/lo uint4.
static __device__ void build_wp_bf(const float* __restrict__ W, uint4* __restrict__ Wp, int tid)
{
    for (int idx = tid; idx < 4096; idx += 256) {
        int lane = idx & 31, ks = (idx >> 5) & 7, t = idx >> 8;
        int g = lane >> 2, tig = lane & 3;
        int j = t * 8 + g;
        int k0 = ks * 16 + 2 * tig;
        float w00 = W[j * 128 + k0],     w01 = W[j * 128 + k0 + 1];
        float w10 = W[j * 128 + k0 + 8], w11 = W[j * 128 + k0 + 9];
        unsigned b0h = pack_bf2(w00, w01);
        unsigned b1h = pack_bf2(w10, w11);
        unsigned b0l = pack_bf2(w00 - ubf_lo(b0h), w01 - ubf_hi(b0h));
        unsigned b1l = pack_bf2(w10 - ubf_lo(b1h), w11 - ubf_hi(b1h));
        Wp[idx] = make_uint4(b0h, b1h, b0l, b1l);
    }
}

// LDG one 64-row tile slice into registers (8 float4 per thread)
static __device__ __forceinline__ void ldg_tile(const float* __restrict__ A, int base, int M,
                                                int tid, float4 v[8])
{
    #pragma unroll
    for (int i = 0; i < 8; i++) {
        int f4 = tid + i * 256;            // 0..2047
        int row = f4 >> 5, c4 = (f4 & 31) * 4;
        v[i] = make_float4(0.f, 0.f, 0.f, 0.f);
        if (base + row < M) v[i] = *(const float4*)&A[(size_t)(base + row) * 128 + c4];
    }
}

// split registers into bf16 hi/lo smem tiles
static __device__ __forceinline__ void store_split(const float4 v[8],
                                                   unsigned short* __restrict__ Ahi,
                                                   unsigned short* __restrict__ Alo, int tid)
{
    #pragma unroll
    for (int i = 0; i < 8; i++) {
        int f4 = tid + i * 256;
        int row = f4 >> 5, c4 = (f4 & 31) * 4;
        unsigned h01 = pack_bf2(v[i].x, v[i].y);
        unsigned h23 = pack_bf2(v[i].z, v[i].w);
        unsigned l01 = pack_bf2(v[i].x - ubf_lo(h01), v[i].y - ubf_hi(h01));
        unsigned l23 = pack_bf2(v[i].z - ubf_lo(h23), v[i].w - ubf_hi(h23));
        *(uint2*)&Ahi[row * AST + c4] = make_uint2(h01, h23);
        *(uint2*)&Alo[row * AST + c4] = make_uint2(l01, l23);
    }
}

// bf16 3-term split mainloop with ldmatrix A-fragment loads.
// Warp tile m32 x n32 (2 mtiles x 4 ntiles), k16 steps.
static __device__ __forceinline__ void mma_mainloop_bf(
    const unsigned short* __restrict__ Ahi, const unsigned short* __restrict__ Alo,
    const uint4* __restrict__ Wp,
    int mwarp, int nwarp, int lane, float acc[2][4][4])
{
    #pragma unroll
    for (int mt = 0; mt < 2; mt++)
        #pragma unroll
        for (int nt = 0; nt < 4; nt++)
            #pragma unroll
            for (int q = 0; q < 4; q++) acc[mt][nt][q] = 0.f;

    // ldmatrix lane->tile addressing: lanes 0-7 tile0 (r,k), 8-15 tile1 (r+8,k),
    // 16-23 tile2 (r,k+8), 24-31 tile3 (r+8,k+8)
    int lrow = (lane & 7) + ((lane >> 3) & 1) * 8;   // row within m16
    int lcol = ((lane >> 4) & 1) * 8;                // col offset within k16

    #pragma unroll
    for (int ks = 0; ks < 8; ks++) {
        int k0 = ks * 16;
        unsigned ah[2][4], al[2][4];
        #pragma unroll
        for (int mt = 0; mt < 2; mt++) {
            int row = mwarp * 32 + mt * 16 + lrow;
            ldsm_x4(ah[mt], &Ahi[row * AST + k0 + lcol]);
            ldsm_x4(al[mt], &Alo[row * AST + k0 + lcol]);
        }
        #pragma unroll
        for (int nt = 0; nt < 4; nt++) {
            int t = nwarp * 4 + nt;
            uint4 w = Wp[(t * 8 + ks) * 32 + lane];
            #pragma unroll
            for (int mt = 0; mt < 2; mt++) {
                mma_bf16(acc[mt][nt], ah[mt][0], ah[mt][1], ah[mt][2], ah[mt][3], w.x, w.y);
                mma_bf16(acc[mt][nt], ah[mt][0], ah[mt][1], ah[mt][2], ah[mt][3], w.z, w.w);
                mma_bf16(acc[mt][nt], al[mt][0], al[mt][1], al[mt][2], al[mt][3], w.x, w.y);
            }
        }
    }
}

// ---------------------------------------------------------------------
// All-GEMM kernel: edge GEMM (blocks [0,1184)) + 4 node GEMMs (74 each).
// out = A @ W^T + b, persistent strided tiles, register-prefetch pipeline.
// ---------------------------------------------------------------------
__global__ __launch_bounds__(256, 2) void gemm_all_kernel(
    const float* __restrict__ h, const float* __restrict__ e,
    const float* __restrict__ WA, const float* __restrict__ bA, float* __restrict__ oA,
    const float* __restrict__ WB, const float* __restrict__ bB, float* __restrict__ oB,
    const float* __restrict__ WD, const float* __restrict__ bD, float* __restrict__ oD,
    const float* __restrict__ WE, const float* __restrict__ bE, float* __restrict__ oE,
    const float* __restrict__ WC, const float* __restrict__ bC, float* __restrict__ oC)
{
    extern __shared__ float s[];
    uint4* Wp = (uint4*)(s + OFF_WP);
    unsigned short* Ahi = (unsigned short*)(s + OFF_AHI);
    unsigned short* Alo = (unsigned short*)(s + OFF_ALO);
    float* bs = s + OFF_BS;

    int tid = threadIdx.x, lane = tid & 31, warp = tid >> 5;
    int mwarp = warp >> 2, nwarp = warp & 3;
    int g = lane >> 2, tig = lane & 3;

    const float* A; const float* W; const float* bias; float* out;
    int M, tiles, tstart, tstride;
    if (blockIdx.x < EDGE_BLKS) {
        A = e; W = WC; bias = bC; out = oC;
        M = N_EDGES; tiles = N_EDGES / TM;           // 12500
        tstart = blockIdx.x; tstride = EDGE_BLKS;
    } else {
        int b = blockIdx.x - EDGE_BLKS;
        int which = b / NODE_BLKS_PER;
        A = h; M = N_NODES; tiles = (N_NODES + TM - 1) / TM;   // 782
        tstart = b % NODE_BLKS_PER; tstride = NODE_BLKS_PER;
        if      (which == 0) { W = WA; bias = bA; out = oA; }
        else if (which == 1) { W = WB; bias = bB; out = oB; }
        else if (which == 2) { W = WD; bias = bD; out = oD; }
        else                 { W = WE; bias = bE; out = oE; }
    }

    build_wp_bf(W, Wp, tid);
    if (tid < 128) bs[tid] = bias[tid];

    float4 v[8];
    if (tstart < tiles) ldg_tile(A, tstart * TM, M, tid, v);   // prefetch first tile

    for (int tile = tstart; tile < tiles; tile += tstride) {
        int base = tile * TM;
        __syncthreads();                   // prev MMA done reading smem
        store_split(v, Ahi, Alo, tid);
        __syncthreads();

        int next = tile + tstride;
        if (next < tiles) ldg_tile(A, next * TM, M, tid, v);   // hide under MMA

        float acc[2][4][4];
        mma_mainloop_bf(Ahi, Alo, Wp, mwarp, nwarp, lane, acc);

        #pragma unroll
        for (int mt = 0; mt < 2; mt++) {
            int r0 = base + mwarp * 32 + mt * 16 + g;
            #pragma unroll
            for (int nt = 0; nt < 4; nt++) {
                int col = nwarp * 32 + nt * 8 + 2 * tig;
                float bx = bs[col], by = bs[col + 1];
                if (r0 < M)
                    *(float2*)&out[(size_t)r0 * 128 + col] =
                        make_float2(acc[mt][nt][0] + bx, acc[mt][nt][1] + by);
                if (r0 + 8 < M)
                    *(float2*)&out[(size_t)(r0 + 8) * 128 + col] =
                        make_float2(acc[mt][nt][2] + bx, acc[mt][nt][3] + by);
            }
        }
    }
}

// ---------------------------------------------------------------------
// Edge epilogue: one warp per edge, grid-stride. Max occupancy.
// enew holds Ce+bC on entry; rewritten in place with final e_new.
// Streaming hints on enew only (measured win in R15).
// ---------------------------------------------------------------------
__global__ __launch_bounds__(256, 6) void edge_epilogue_kernel(
    float* __restrict__ enew,
    const float* __restrict__ Bh, const float* __restrict__ Dh, const float* __restrict__ Eh,
    const int* __restrict__ src, const int* __restrict__ dst, const int* __restrict__ mask,
    const float* __restrict__ diff, const float* __restrict__ dist, const float* __restrict__ dirn,
    float* __restrict__ hsumbuf, float* __restrict__ stats)
{
    __shared__ float rs[1024], rq[1024];
    int tid = threadIdx.x, lane = tid & 31, warp = tid >> 5;
    int c0 = lane * 4;
    int gw = blockIdx.x * 8 + warp;
    int nw = gridDim.x * 8;

    float4 csum = make_float4(0.f, 0.f, 0.f, 0.f);
    float4 csq  = make_float4(0.f, 0.f, 0.f, 0.f);

    for (int i = gw; i < N_EDGES; i += nw) {
        int si = __ldg(&src[i]), di = __ldg(&dst[i]);
        float4 ce  = __ldcs((const float4*)&enew[(size_t)i * 128 + c0]);
        float4 dh  = *(const float4*)&Dh[(size_t)di * 128 + c0];
        float4 ehv = *(const float4*)&Eh[(size_t)si * 128 + c0];
        float4 de = make_float4(dh.x - ehv.x, dh.y - ehv.y, dh.z - ehv.z, dh.w - ehv.w);
        float4 en = make_float4(de.x + ce.x, de.y + ce.y, de.z + ce.z, de.w + ce.w);

        float ss = en.x * en.x + en.y * en.y + en.z * en.z + en.w * en.w;
        #pragma unroll
        for (int o = 16; o > 0; o >>= 1) ss += __shfl_xor_sync(0xffffffffu, ss, o);
        float sigma = expf(-0.5f * sqrtf(ss));

        float ddv = __ldg(&dist[i]);
        float df0 = __ldg(&diff[2 * i]), df1 = __ldg(&diff[2 * i + 1]);
        float ed0, ed1;
        if (ddv > 0.f) { ed0 = df0 / ddv; ed1 = df1 / ddv; } else { ed0 = df0; ed1 = df1; }
        float vs0 = __ldg(&dirn[2 * si]), vs1 = __ldg(&dirn[2 * si + 1]);
        float vd0 = __ldg(&dirn[2 * di]), vd1 = __ldg(&dirn[2 * di + 1]);
        float uv  = vs0 * vd0 + vs1 * vd1;
        float ehd = ed0 * vd0 + ed1 * vd1;
        float fgate = 0.5f * (1.f - ehd) * uv * sigma;
        float gate = (__ldg(&mask[i]) == 1) ? fgate : sigma;

        float4 bh = *(const float4*)&Bh[(size_t)si * 128 + c0];
        float4 hs = make_float4((bh.x + de.x) * gate, (bh.y + de.y) * gate,
                                (bh.z + de.z) * gate, (bh.w + de.w) * gate);
        atomicAdd((float4*)&hsumbuf[(size_t)di * 128 + c0], hs);
        __stcs((float4*)&enew[(size_t)i * 128 + c0], en);

        csum.x += en.x; csum.y += en.y; csum.z += en.z; csum.w += en.w;
        csq.x += en.x * en.x; csq.y += en.y * en.y;
        csq.z += en.z * en.z; csq.w += en.w * en.w;
    }

    *(float4*)&rs[warp * 128 + c0] = csum;
    *(float4*)&rq[warp * 128 + c0] = csq;
    __syncthreads();
    if (tid < 128) {
        float s1 = 0.f, q1 = 0.f;
        #pragma unroll
        for (int w = 0; w < 8; w++) { s1 += rs[w * 128 + tid]; q1 += rq[w * 128 + tid]; }
        atomicAdd(&stats[tid], s1);
        atomicAdd(&stats[128 + tid], q1);
    }
}

// ---------------------------------------------------------------------
// hpre = Ah + hsum; accumulate h column stats
// ---------------------------------------------------------------------
__global__ __launch_bounds__(256) void hpre_kernel(
    const float* __restrict__ Ah, const float* __restrict__ hsumbuf,
    float* __restrict__ hpre, float* __restrict__ stats)
{
    __shared__ float red[2048];
    int tid = threadIdx.x, lane = tid & 31, warp = tid >> 5;
    int c0 = lane * 4;
    int gw = blockIdx.x * 8 + warp;
    int nw = gridDim.x * 8;

    float4 csum = make_float4(0.f, 0.f, 0.f, 0.f);
    float4 csq  = make_float4(0.f, 0.f, 0.f, 0.f);

    for (int r = gw; r < N_NODES; r += nw) {
        float4 a = *(const float4*)&Ah[(size_t)r * 128 + c0];
        float4 hv = *(const float4*)&hsumbuf[(size_t)r * 128 + c0];
        float4 p = make_float4(a.x + hv.x, a.y + hv.y, a.z + hv.z, a.w + hv.w);
        *(float4*)&hpre[(size_t)r * 128 + c0] = p;
        csum.x += p.x; csum.y += p.y; csum.z += p.z; csum.w += p.w;
        csq.x += p.x * p.x; csq.y += p.y * p.y; csq.z += p.z * p.z; csq.w += p.w * p.w;
    }
    *(float4*)&red[warp * 128 + c0] = csum;
    *(float4*)&red[1024 + warp * 128 + c0] = csq;
    __syncthreads();
    if (tid < 128) {
        float s1 = 0.f, q1 = 0.f;
        #pragma unroll
        for (int w = 0; w < 8; w++) { s1 += red[w * 128 + tid]; q1 += red[1024 + w * 128 + tid]; }
        atomicAdd(&stats[256 + tid], s1);
        atomicAdd(&stats[384 + tid], q1);
    }
}

// ---------------------------------------------------------------------
__global__ void finalize_kernel(const float* __restrict__ st, float* __restrict__ bnout, float invcount)
{
    int t = threadIdx.x;
    if (t < 128) {
        float mean = st[t] * invcount;
        float var  = st[128 + t] * invcount - mean * mean;
        bnout[t] = mean;
        bnout[128 + t] = rsqrtf(var + EPSBN);
    }
}

// dummy launch-slot shifters so ncu (-s 5 -c 1) captures gemm_all
__global__ void dummy_kernel() {}

// out = resid + relu(gamma*(pre-mean)*invstd + beta), elementwise, float4
__global__ void apply_kernel(const float* __restrict__ pre, const float* __restrict__ resid,
                             const float* __restrict__ gamma, const float* __restrict__ beta,
                             const float* __restrict__ bn, float* __restrict__ out, int total4)
{
    int idx = blockIdx.x * blockDim.x + threadIdx.x;
    int stride = gridDim.x * blockDim.x;
    for (; idx < total4; idx += stride) {
        int c0 = (idx & 31) * 4;
        float4 m  = *(const float4*)&bn[c0];
        float4 iv = *(const float4*)&bn[128 + c0];
        float4 g  = *(const float4*)&gamma[c0];
        float4 b  = *(const float4*)&beta[c0];
        float4 p  = ((const float4*)pre)[idx];
        float4 rr = ((const float4*)resid)[idx];
        float4 o;
        o.x = fmaxf((p.x - m.x) * iv.x * g.x + b.x, 0.f) + rr.x;
        o.y = fmaxf((p.y - m.y) * iv.y * g.y + b.y, 0.f) + rr.y;
        o.z = fmaxf((p.z - m.z) * iv.z * g.z + b.z, 0.f) + rr.z;
        o.w = fmaxf((p.w - m.w) * iv.w * g.w + b.w, 0.f) + rr.w;
        ((float4*)out)[idx] = o;
    }
}

// ---------------------------------------------------------------------
extern "C" void kernel_launch(void* const* d_in, const int* in_sizes, int n_in,
                              void* d_out, int out_size)
{
    const float* h    = (const float*)d_in[0];
    const float* e    = (const float*)d_in[1];
    const int*   src  = (const int*)d_in[2];
    const int*   dst  = (const int*)d_in[3];
    const int*   mask = (const int*)d_in[4];
    const float* diff = (const float*)d_in[5];
    const float* dist = (const float*)d_in[6];
    const float* dirn = (const float*)d_in[7];
    const float* WA = (const float*)d_in[8];   const float* bA = (const float*)d_in[9];
    const float* WB = (const float*)d_in[10];  const float* bB = (const float*)d_in[11];
    const float* WC = (const float*)d_in[12];  const float* bC = (const float*)d_in[13];
    const float* WD = (const float*)d_in[14];  const float* bD = (const float*)d_in[15];
    const float* WE = (const float*)d_in[16];  const float* bE = (const float*)d_in[17];
    const float* gh = (const float*)d_in[18];  const float* betah = (const float*)d_in[19];
    const float* ge = (const float*)d_in[20];  const float* betae = (const float*)d_in[21];
    float* out = (float*)d_out;

    float *Ah, *Bh, *Dh, *Eh, *hsum, *hpre, *enew, *stats, *bn;
    cudaGetSymbolAddress((void**)&Ah,   g_Ah);
    cudaGetSymbolAddress((void**)&Bh,   g_Bh);
    cudaGetSymbolAddress((void**)&Dh,   g_Dh);
    cudaGetSymbolAddress((void**)&Eh,   g_Eh);
    cudaGetSymbolAddress((void**)&hsum, g_hsum);
    cudaGetSymbolAddress((void**)&hpre, g_hpre);
    cudaGetSymbolAddress((void**)&enew, g_enew);
    cudaGetSymbolAddress((void**)&stats, g_stats);
    cudaGetSymbolAddress((void**)&bn,   g_bn);

    cudaFuncSetAttribute(gemm_all_kernel, cudaFuncAttributeMaxDynamicSharedMemorySize, SM_BYTES);

    cudaMemsetAsync(hsum, 0, (size_t)N_NODES * DD * sizeof(float));   // launch 1
    cudaMemsetAsync(stats, 0, 512 * sizeof(float));                   // launch 2

    dummy_kernel<<<1, 32>>>();                                        // launch 3
    dummy_kernel<<<1, 32>>>();                                        // launch 4
    dummy_kernel<<<1, 32>>>();                                        // launch 5

    gemm_all_kernel<<<ALL_BLKS, 256, SM_BYTES>>>(                     // launch 6 (ncu captures)
        h, e,
        WA, bA, Ah,
        WB, bB, Bh,
        WD, bD, Dh,
        WE, bE, Eh,
        WC, bC, enew);

    edge_epilogue_kernel<<<2368, 256>>>(enew, Bh, Dh, Eh, src, dst, mask,
                                        diff, dist, dirn, hsum, stats);

    finalize_kernel<<<1, 128>>>(stats, bn, 1.0f / (float)N_EDGES);
    hpre_kernel<<<296, 256>>>(Ah, hsum, hpre, stats);
    finalize_kernel<<<1, 128>>>(stats + 256, bn + 256, 1.0f / (float)N_NODES);

    apply_kernel<<<1024, 256>>>(hpre, h, gh, betah, bn + 256, out, N_NODES * 32);
    apply_kernel<<<4096, 256>>>(enew, e, ge, betae, bn, out + (size_t)N_NODES * DD, N_EDGES * 32);
}